// round 15
// baseline (speedup 1.0000x reference)
#include <cuda_runtime.h>
#include <cstdint>

// Problem constants (fixed by the reference setup)
#define B_SZ      256
#define D_SZ      8192
#define S_SZ      8
#define W_SZ      4
#define NSLOTS    2048
#define STATE_LEN 3

// One thread per (b, d) pair. Consecutive threads cover consecutive d, so
// x/out accesses (32B/thread, contiguous within warp), weight (16B), and
// state rows (12B) are all coalesced.
__global__ __launch_bounds__(256) void conv1d_update_kernel(
    const float* __restrict__ x,            // [B, D, S]
    const float* __restrict__ weight,       // [D, W]
    const float* __restrict__ conv_states,  // [NSLOTS, D, STATE_LEN] (old)
    const int* __restrict__ cache_indices,  // [B] int32 (jax x64-disabled)
    const int* __restrict__ residual_p,     // scalar int32
    const int* __restrict__ pad_p,          // scalar int32
    float* __restrict__ out,                // [B, D, S]
    float* __restrict__ new_states)         // [NSLOTS, D, STATE_LEN] (pre-copied)
{
    const int t = blockIdx.x * blockDim.x + threadIdx.x;
    if (t >= B_SZ * D_SZ) return;

    const int b = t >> 13;          // t / 8192
    const int d = t & (D_SZ - 1);   // t % 8192

    const int pad = *pad_p;
    const int idx = cache_indices[b];
    const bool valid = (idx != pad);
    const int safe = valid ? idx : 0;

    // Old state: 3 floats
    const float* sp = conv_states + ((size_t)safe * D_SZ + d) * STATE_LEN;
    const float c0 = sp[0];
    const float c1 = sp[1];
    const float c2 = sp[2];

    // x row: 8 floats, two float4 loads (base is 32B aligned per thread)
    const float4 xa = *reinterpret_cast<const float4*>(x + (size_t)t * S_SZ);
    const float4 xb = *reinterpret_cast<const float4*>(x + (size_t)t * S_SZ + 4);

    // weight row: 4 floats
    const float4 wv = *reinterpret_cast<const float4*>(weight + (size_t)d * W_SZ);

    // cat = [c0, c1, c2, x0..x7]
    float cat[STATE_LEN + S_SZ];
    cat[0] = c0;   cat[1] = c1;   cat[2] = c2;
    cat[3] = xa.x; cat[4] = xa.y; cat[5] = xa.z; cat[6] = xa.w;
    cat[7] = xb.x; cat[8] = xb.y; cat[9] = xb.z; cat[10] = xb.w;

    const int residual = *residual_p;

    float o[S_SZ];
#pragma unroll
    for (int s = 0; s < S_SZ; s++) {
        float acc = cat[s] * wv.x;
        acc = fmaf(cat[s + 1], wv.y, acc);
        acc = fmaf(cat[s + 2], wv.z, acc);
        acc = fmaf(cat[s + 3], wv.w, acc);
        if (residual) acc += cat[s + STATE_LEN];
        o[s] = acc;
    }

    *reinterpret_cast<float4*>(out + (size_t)t * S_SZ) =
        make_float4(o[0], o[1], o[2], o[3]);
    *reinterpret_cast<float4*>(out + (size_t)t * S_SZ + 4) =
        make_float4(o[4], o[5], o[6], o[7]);

    // Scatter new state = last STATE_LEN elements of x
    if (valid) {
        float* np = new_states + ((size_t)idx * D_SZ + d) * STATE_LEN;
        np[0] = xb.y;  // x[5]
        np[1] = xb.z;  // x[6]
        np[2] = xb.w;  // x[7]
    }
}

extern "C" void kernel_launch(void* const* d_in, const int* in_sizes, int n_in,
                              void* d_out, int out_size)
{
    const float* x           = (const float*)d_in[0];
    const float* weight      = (const float*)d_in[1];
    const float* conv_states = (const float*)d_in[2];
    const int*   cache_idx   = (const int*)d_in[3];
    const int*   residual_p  = (const int*)d_in[4];
    const int*   pad_p       = (const int*)d_in[5];

    float* out        = (float*)d_out;
    float* new_states = out + (size_t)B_SZ * D_SZ * S_SZ;

    // 1) Bulk copy of the state table (reference rewrites all of it).
    //    Rows at cache_indices are then overwritten by the kernel; stream
    //    ordering guarantees copy-before-scatter.
    cudaMemcpyAsync(new_states, conv_states,
                    (size_t)NSLOTS * D_SZ * STATE_LEN * sizeof(float),
                    cudaMemcpyDeviceToDevice);

    // 2) Conv + residual + state scatter.
    const int total = B_SZ * D_SZ;
    const int threads = 256;
    const int blocks = (total + threads - 1) / threads;
    conv1d_update_kernel<<<blocks, threads>>>(
        x, weight, conv_states, cache_idx, residual_p, pad_p, out, new_states);
}

// round 16
// speedup vs baseline: 1.0986x; 1.0986x over previous
#include <cuda_runtime.h>
#include <cstdint>

// Problem constants (fixed by the reference setup)
#define B_SZ      256
#define D_SZ      8192
#define S_SZ      8
#define W_SZ      4
#define NSLOTS    2048
#define STATE_LEN 3

#define CONV_BLOCKS  ((B_SZ * D_SZ) / 256)                    // 8192
#define ROWS_TOTAL   (NSLOTS * D_SZ)                          // 16,777,216 state rows
#define COPY_BLOCKS  (ROWS_TOTAL / 4 / 256)                   // 16384 (4 rows/thread)

// slot -> (b+1) if slot is gathered this step, else 0
__device__ int g_slot_flag[NSLOTS];

// Single block: zero the flag table, then scatter b+1 for valid cache slots.
__global__ __launch_bounds__(256) void build_flags_kernel(
    const int* __restrict__ cache_indices,
    const int* __restrict__ pad_p)
{
    const int tid = threadIdx.x;
#pragma unroll
    for (int j = 0; j < NSLOTS / 256; j++)
        g_slot_flag[tid + j * 256] = 0;
    __syncthreads();
    const int idx = cache_indices[tid];
    if (idx != *pad_p)
        g_slot_flag[idx] = tid + 1;
}

// Fused kernel:
//   blocks [0, CONV_BLOCKS):  conv + residual + state scatter (one thread per (b,d))
//   blocks [CONV_BLOCKS, ..): copy unmodified state rows (4 rows = 3 float4 per thread),
//                             skipping slots that the conv part overwrites.
__global__ __launch_bounds__(256) void conv1d_fused_kernel(
    const float* __restrict__ x,            // [B, D, S]
    const float* __restrict__ weight,       // [D, W]
    const float* __restrict__ conv_states,  // [NSLOTS, D, STATE_LEN] (old)
    const int* __restrict__ cache_indices,  // [B] int32
    const int* __restrict__ residual_p,     // scalar int32
    const int* __restrict__ pad_p,          // scalar int32
    float* __restrict__ out,                // [B, D, S]
    float* __restrict__ new_states)         // [NSLOTS, D, STATE_LEN]
{
    const int bid = blockIdx.x;

    if (bid < CONV_BLOCKS) {
        // ---------------- conv path ----------------
        const int t = bid * 256 + threadIdx.x;      // (b, d) index
        const int b = t >> 13;                      // t / 8192
        const int d = t & (D_SZ - 1);               // t % 8192

        const int pad = *pad_p;
        const int idx = cache_indices[b];
        const bool valid = (idx != pad);
        const int safe = valid ? idx : 0;

        // Old state: 3 floats (warp-contiguous 384B)
        const float* sp = conv_states + ((size_t)safe * D_SZ + d) * STATE_LEN;
        const float c0 = sp[0];
        const float c1 = sp[1];
        const float c2 = sp[2];

        // x row: 8 floats, two float4 loads
        const float4 xa = *reinterpret_cast<const float4*>(x + (size_t)t * S_SZ);
        const float4 xb = *reinterpret_cast<const float4*>(x + (size_t)t * S_SZ + 4);

        // weight row: 4 floats
        const float4 wv = *reinterpret_cast<const float4*>(weight + (size_t)d * W_SZ);

        float cat[STATE_LEN + S_SZ];
        cat[0] = c0;   cat[1] = c1;   cat[2] = c2;
        cat[3] = xa.x; cat[4] = xa.y; cat[5] = xa.z; cat[6] = xa.w;
        cat[7] = xb.x; cat[8] = xb.y; cat[9] = xb.z; cat[10] = xb.w;

        const int residual = *residual_p;

        float o[S_SZ];
#pragma unroll
        for (int s = 0; s < S_SZ; s++) {
            float acc = cat[s] * wv.x;
            acc = fmaf(cat[s + 1], wv.y, acc);
            acc = fmaf(cat[s + 2], wv.z, acc);
            acc = fmaf(cat[s + 3], wv.w, acc);
            if (residual) acc += cat[s + STATE_LEN];
            o[s] = acc;
        }

        *reinterpret_cast<float4*>(out + (size_t)t * S_SZ) =
            make_float4(o[0], o[1], o[2], o[3]);
        *reinterpret_cast<float4*>(out + (size_t)t * S_SZ + 4) =
            make_float4(o[4], o[5], o[6], o[7]);

        // Scatter new state = x[..., 5:8] from registers (12B/thread, warp-contiguous)
        if (valid) {
            float* np = new_states + ((size_t)idx * D_SZ + d) * STATE_LEN;
            np[0] = xb.y;
            np[1] = xb.z;
            np[2] = xb.w;
        }
    } else {
        // ---------------- copy path ----------------
        // Thread handles 4 consecutive state rows = 48B = 3 float4.
        const int tid = (bid - CONV_BLOCKS) * 256 + threadIdx.x;
        const int r0 = tid * 4;                       // first row index
        const int slot = r0 >> 13;                    // r0 / 8192 (warp-uniform)

        if (g_slot_flag[slot] != 0) return;           // conv part writes this slot

        const float4* src = reinterpret_cast<const float4*>(
            conv_states + (size_t)r0 * STATE_LEN);
        float4* dst = reinterpret_cast<float4*>(
            new_states + (size_t)r0 * STATE_LEN);

        const float4 v0 = src[0];
        const float4 v1 = src[1];
        const float4 v2 = src[2];
        dst[0] = v0;
        dst[1] = v1;
        dst[2] = v2;
    }
}

extern "C" void kernel_launch(void* const* d_in, const int* in_sizes, int n_in,
                              void* d_out, int out_size)
{
    const float* x           = (const float*)d_in[0];
    const float* weight      = (const float*)d_in[1];
    const float* conv_states = (const float*)d_in[2];
    const int*   cache_idx   = (const int*)d_in[3];
    const int*   residual_p  = (const int*)d_in[4];
    const int*   pad_p       = (const int*)d_in[5];

    float* out        = (float*)d_out;
    float* new_states = out + (size_t)B_SZ * D_SZ * S_SZ;

    build_flags_kernel<<<1, 256>>>(cache_idx, pad_p);

    conv1d_fused_kernel<<<CONV_BLOCKS + COPY_BLOCKS, 256>>>(
        x, weight, conv_states, cache_idx, residual_p, pad_p, out, new_states);
}

// round 17
// speedup vs baseline: 1.1204x; 1.0198x over previous
#include <cuda_runtime.h>
#include <cstdint>

// Problem constants (fixed by the reference setup)
#define B_SZ      256
#define D_SZ      8192
#define S_SZ      8
#define W_SZ      4
#define NSLOTS    2048
#define STATE_LEN 3

#define CONV_BLOCKS  ((B_SZ * D_SZ) / 256)     // 8192 blocks, 1 thread per (b,d)
#define ROWS_TOTAL   (NSLOTS * D_SZ)           // 16,777,216 state rows
#define COPY_BLOCKS  (ROWS_TOTAL / 4 / 256)    // 16384 blocks, 4 rows/thread

// Single fused kernel:
//   blocks [0, CONV_BLOCKS):  conv + residual + state scatter (one thread per (b,d))
//   blocks [CONV_BLOCKS, ..): copy unmodified state rows (4 rows = 3 float4/thread).
//     Each copy block covers 1024 contiguous rows, all within ONE slot
//     (8192 rows per slot, blocks 1024-row aligned), so the "is this slot
//     overwritten by the scatter?" test is done cooperatively in-block:
//     thread i checks cache_indices[i] == slot, reduced via __syncthreads_or.
__global__ __launch_bounds__(256) void conv1d_fused_kernel(
    const float* __restrict__ x,            // [B, D, S]
    const float* __restrict__ weight,       // [D, W]
    const float* __restrict__ conv_states,  // [NSLOTS, D, STATE_LEN] (old)
    const int* __restrict__ cache_indices,  // [B] int32
    const int* __restrict__ residual_p,     // scalar int32
    const int* __restrict__ pad_p,          // scalar int32
    float* __restrict__ out,                // [B, D, S]
    float* __restrict__ new_states)         // [NSLOTS, D, STATE_LEN]
{
    const int bid = blockIdx.x;

    if (bid < CONV_BLOCKS) {
        // ---------------- conv path ----------------
        const int t = bid * 256 + threadIdx.x;      // (b, d) index
        const int b = t >> 13;                      // t / 8192
        const int d = t & (D_SZ - 1);               // t % 8192

        const int pad = *pad_p;
        const int idx = cache_indices[b];
        const bool valid = (idx != pad);
        const int safe = valid ? idx : 0;

        // Old state: 3 floats (warp-contiguous 384B)
        const float* sp = conv_states + ((size_t)safe * D_SZ + d) * STATE_LEN;
        const float c0 = sp[0];
        const float c1 = sp[1];
        const float c2 = sp[2];

        // x row: 8 floats, two float4 loads
        const float4 xa = *reinterpret_cast<const float4*>(x + (size_t)t * S_SZ);
        const float4 xb = *reinterpret_cast<const float4*>(x + (size_t)t * S_SZ + 4);

        // weight row: 4 floats
        const float4 wv = *reinterpret_cast<const float4*>(weight + (size_t)d * W_SZ);

        float cat[STATE_LEN + S_SZ];
        cat[0] = c0;   cat[1] = c1;   cat[2] = c2;
        cat[3] = xa.x; cat[4] = xa.y; cat[5] = xa.z; cat[6] = xa.w;
        cat[7] = xb.x; cat[8] = xb.y; cat[9] = xb.z; cat[10] = xb.w;

        const int residual = *residual_p;

        float o[S_SZ];
#pragma unroll
        for (int s = 0; s < S_SZ; s++) {
            float acc = cat[s] * wv.x;
            acc = fmaf(cat[s + 1], wv.y, acc);
            acc = fmaf(cat[s + 2], wv.z, acc);
            acc = fmaf(cat[s + 3], wv.w, acc);
            if (residual) acc += cat[s + STATE_LEN];
            o[s] = acc;
        }

        *reinterpret_cast<float4*>(out + (size_t)t * S_SZ) =
            make_float4(o[0], o[1], o[2], o[3]);
        *reinterpret_cast<float4*>(out + (size_t)t * S_SZ + 4) =
            make_float4(o[4], o[5], o[6], o[7]);

        // Scatter new state = x[..., 5:8] from registers (12B/thread, contiguous)
        if (valid) {
            float* np = new_states + ((size_t)idx * D_SZ + d) * STATE_LEN;
            np[0] = xb.y;
            np[1] = xb.z;
            np[2] = xb.w;
        }
    } else {
        // ---------------- copy path ----------------
        const int cb   = bid - CONV_BLOCKS;
        const int tid  = cb * 256 + threadIdx.x;
        const int r0   = tid * 4;                 // first of 4 rows for this thread
        const int slot = (cb * 1024) >> 13;       // block-uniform slot id

        // Cooperative gathered-slot test (B_SZ == blockDim == 256).
        const int ci  = cache_indices[threadIdx.x];
        const int pad = *pad_p;
        const int hit = __syncthreads_or((ci == slot) && (ci != pad));
        if (hit) return;                           // conv path overwrites this slot

        const float4* src = reinterpret_cast<const float4*>(
            conv_states + (size_t)r0 * STATE_LEN);
        float4* dst = reinterpret_cast<float4*>(
            new_states + (size_t)r0 * STATE_LEN);

        const float4 v0 = src[0];
        const float4 v1 = src[1];
        const float4 v2 = src[2];
        dst[0] = v0;
        dst[1] = v1;
        dst[2] = v2;
    }
}

extern "C" void kernel_launch(void* const* d_in, const int* in_sizes, int n_in,
                              void* d_out, int out_size)
{
    const float* x           = (const float*)d_in[0];
    const float* weight      = (const float*)d_in[1];
    const float* conv_states = (const float*)d_in[2];
    const int*   cache_idx   = (const int*)d_in[3];
    const int*   residual_p  = (const int*)d_in[4];
    const int*   pad_p       = (const int*)d_in[5];

    float* out        = (float*)d_out;
    float* new_states = out + (size_t)B_SZ * D_SZ * S_SZ;

    conv1d_fused_kernel<<<CONV_BLOCKS + COPY_BLOCKS, 256>>>(
        x, weight, conv_states, cache_idx, residual_p, pad_p, out, new_states);
}